// round 9
// baseline (speedup 1.0000x reference)
#include <cuda_runtime.h>
#include <cuda_fp16.h>
#include <stdint.h>
#include <math.h>

#define T_TOK 2048
#define DIM   512
#define MOE   256
#define NE    64
#define NG    8
#define TOPKG 4
#define KSEL  8
#define RSCALE 2.5f
#define CAP   1024
#define ROWT  64
#define THREADS 512
#define NCTA  148
#define NITEMS 2048

__device__ int   g_count[NE];
__device__ int   g_rows[NE][CAP];
__device__ float g_wt[NE][CAP];
__device__ int   g_tile;
__device__ int   g_ready[NE];
__device__ int   g_bar;

// fp16 panels (vector-fragment order), packed half2 words. 65536 words/expert.
__device__ uint32_t g_w1h[NE * 65536];
__device__ uint32_t g_w3h[NE * 65536];
__device__ uint32_t g_w2h[NE * 65536];
__device__ uint32_t g_xh[T_TOK * 256];

// ---------------------------------------------------------------------------
// ffn smem word map:
//  [0,64) rows_s  [64,128) wt_s
//  ring base 128: phase A stride STA=4608 (W1 2048 | W3 2048 | X 512), 8 bufs
//                 phase B stride STB=4096 (W2), 8 bufs (overlaid)
//  HBW = 128 + 8*4608 = 36992 : H planes 16c x 4mf x 128 = 8192 words
//  gate/convert phases reuse the same region as scratch.
// ---------------------------------------------------------------------------
#define STA 4608
#define STB 4096
#define HBW 36992
#define SMEM_W (36992 + 8192)
#define FFN_SMEM (SMEM_W * 4)

#define CP16(dst_b, src) \
    asm volatile("cp.async.cg.shared.global [%0], [%1], 16;" :: "r"(dst_b), "l"(src))
#define CP4(dst_b, src) \
    asm volatile("cp.async.ca.shared.global [%0], [%1], 4;" :: "r"(dst_b), "l"(src))
#define CP_COMMIT() asm volatile("cp.async.commit_group;" ::: "memory")
#define CP_WAIT6()  asm volatile("cp.async.wait_group 6;" ::: "memory")
#define CP_WAIT0()  asm volatile("cp.async.wait_group 0;" ::: "memory")

__device__ __forceinline__ uint32_t packh2(float lo, float hi) {
    __half2 h = __floats2half2_rn(lo, hi);
    return *(uint32_t*)&h;
}
__device__ __forceinline__ void mma16(float* d, uint32_t a0, uint32_t a1,
                                      uint32_t a2, uint32_t a3,
                                      uint32_t b0, uint32_t b1) {
    asm volatile(
        "mma.sync.aligned.m16n8k16.row.col.f32.f16.f16.f32 "
        "{%0,%1,%2,%3}, {%4,%5,%6,%7}, {%8,%9}, {%0,%1,%2,%3};"
        : "+f"(d[0]), "+f"(d[1]), "+f"(d[2]), "+f"(d[3])
        : "r"(a0), "r"(a1), "r"(a2), "r"(a3), "r"(b0), "r"(b1));
}

// ---------------------------------------------------------------------------
__global__ void zero_small() {
    int t = threadIdx.x;
    if (t < NE) { g_count[t] = 0; g_ready[t] = 0; }
    if (t == NE)     g_tile = 0;
    if (t == NE + 1) g_bar  = 0;
}

// ---------------------------------------------------------------------------
// THE kernel: gate + x-convert + out-zero | grid sync | convert+ffn queue.
// 148 CTAs x 512 threads, all resident (1 CTA/SM via smem).
// ---------------------------------------------------------------------------
__global__ __launch_bounds__(THREADS, 1) void moe_kernel(
    const float* __restrict__ x,
    const float* __restrict__ gate_w,
    const float* __restrict__ gate_b,
    const float* __restrict__ w1,
    const float* __restrict__ w3,
    const float* __restrict__ w2,
    float* __restrict__ out)
{
    extern __shared__ uint32_t sm[];
    __shared__ int cur_t;

    const int cta = blockIdx.x;
    const int tid = threadIdx.x;
    const int lane = tid & 31, wid = tid >> 5;
    const int g    = lane >> 2, tig = lane & 3;
    const int mg   = wid >> 3, nw = wid & 7;

    float* ps = (float*)sm;

    // ================= Phase 1: gate, 8 tokens per CTA per round ============
    {
        float* xs     = ps;                         // [8][512]
        float (*gws)[68] = (float(*)[68])(ps + 4096);
        float* scores = ps + 4096 + 4352;           // [8][64]
        float* sb     = scores + 512;               // [8][64]
        const int tg = tid >> 6, te = tid & 63;

        for (int round = 0; round < 2; round++) {
            const int t = round * NCTA * 8 + cta * 8 + tg;
            const bool valid = (t < T_TOK);
            __syncthreads();
            if (valid) {
                const float4* xr = (const float4*)(x + (size_t)t * DIM);
                ((float4*)(xs + tg * DIM))[te]      = xr[te];
                ((float4*)(xs + tg * DIM))[64 + te] = xr[64 + te];
            }
            __syncthreads();

            float acc = 0.0f;
            const float4* gw4 = (const float4*)gate_w;
            for (int kc = 0; kc < DIM; kc += 64) {
                __syncthreads();
                #pragma unroll
                for (int j = 0; j < 2; j++) {
                    int idx = j * 512 + tid;
                    int e   = idx >> 4;
                    int m4  = idx & 15;
                    *(float4*)&gws[e][m4 * 4] = gw4[(size_t)e * (DIM/4) + (kc >> 2) + m4];
                }
                __syncthreads();
                #pragma unroll
                for (int kk = 0; kk < 64; kk += 4) {
                    float4 wv = *(float4*)&gws[te][kk];
                    float4 xv = *(float4*)&xs[tg * DIM + kc + kk];
                    acc += xv.x * wv.x + xv.y * wv.y + xv.z * wv.z + xv.w * wv.w;
                }
            }
            float sc = 1.0f / (1.0f + expf(-acc));
            scores[tg * 64 + te] = sc;
            sb[tg * 64 + te]     = sc + gate_b[te];
            __syncthreads();

            if (te == 0 && valid) {
                float* sbT = sb + tg * 64;
                float* scT = scores + tg * 64;
                const float NEG = -3.0e38f;
                float gsc[NG];
                #pragma unroll
                for (int gg = 0; gg < NG; gg++) {
                    float m1 = NEG, m2 = NEG;
                    #pragma unroll
                    for (int j = 0; j < 8; j++) {
                        float v = sbT[gg * 8 + j];
                        if (v > m1) { m2 = m1; m1 = v; }
                        else if (v > m2) { m2 = v; }
                    }
                    gsc[gg] = m1 + m2;
                }
                bool gsel[NG];
                #pragma unroll
                for (int gg = 0; gg < NG; gg++) gsel[gg] = false;
                for (int it = 0; it < TOPKG; it++) {
                    int bg = -1; float bv = NEG;
                    #pragma unroll
                    for (int gg = 0; gg < NG; gg++)
                        if (!gsel[gg] && gsc[gg] > bv) { bv = gsc[gg]; bg = gg; }
                    gsel[bg] = true;
                }
                for (int e = 0; e < NE; e++)
                    if (!gsel[e >> 3]) sbT[e] = NEG;
                int   idxs[KSEL];
                float wts[KSEL];
                float wsum = 0.0f;
                for (int k = 0; k < KSEL; k++) {
                    int bi = 0; float bv = NEG;
                    for (int e = 0; e < NE; e++)
                        if (sbT[e] > bv) { bv = sbT[e]; bi = e; }
                    sbT[bi] = NEG;
                    idxs[k] = bi;
                    wts[k]  = scT[bi];
                    wsum   += wts[k];
                }
                float inv = RSCALE / wsum;
                for (int k = 0; k < KSEL; k++) {
                    int e = idxs[k];
                    int pos = atomicAdd(&g_count[e], 1);
                    if (pos < CAP) {
                        g_rows[e][pos] = t;
                        g_wt[e][pos]   = wts[k] * inv;
                    }
                }
            }
        }
    }

    // ================= Phase 2: x -> half2, zero out ========================
    {
        const int gtid = cta * THREADS + tid;
        const int NT   = NCTA * THREADS;
        const float2* x2 = (const float2*)x;
        for (int i = gtid; i < T_TOK * 256; i += NT) {
            float2 v = x2[i];
            g_xh[i] = packh2(v.x, v.y);
        }
        float4* out4 = (float4*)out;
        for (int i = gtid; i < T_TOK * DIM / 4; i += NT)
            out4[i] = make_float4(0.f, 0.f, 0.f, 0.f);
    }

    // ================= grid-wide barrier ====================================
    __syncthreads();
    if (tid == 0) {
        __threadfence();
        atomicAdd(&g_bar, 1);
        while (*(volatile int*)&g_bar < NCTA) {}
        __threadfence();
    }
    __syncthreads();

    // ================= Phase 3: queue of convert items then tile items ======
    uint32_t smem_b;
    asm("{ .reg .u64 t; cvta.to.shared.u64 t, %1; cvt.u32.u64 %0, t; }"
        : "=r"(smem_b) : "l"(sm));

    const int xrow = tid >> 3, xkp = tid & 7;
    const uint32_t xw = ((xrow >> 4) * 128 + ((xrow & 7) * 4 + (xkp & 3)) * 4 +
                        ((xrow >> 3) & 1) + 2 * (xkp >> 2)) * 4;

    int*   rows_s = (int*)sm;
    float* wt_s   = (float*)(sm + 64);
    float (*cs)[516] = (float(*)[516])(ps + 128);   // convert scratch

    for (;;) {
        __syncthreads();
        if (tid == 0) cur_t = atomicAdd(&g_tile, 1);
        __syncthreads();
        const int item = cur_t;
        if (item >= NITEMS) break;

        if (item < 1024) {
            // ---------------- convert item: e = item>>4, s = item&15 --------
            const int e = item >> 4, s = item & 15;
            if (s < 8) {
                // 4 k16-chunks of w1 AND w3
                for (int cc = 0; cc < 4; cc++) {
                    const int chunk = s * 4 + cc;
                    for (int mat = 0; mat < 2; mat++) {
                        const float* src = mat ? w3 : w1;
                        uint32_t*    dst = mat ? g_w3h : g_w1h;
                        const float4* s4 = (const float4*)src +
                                           (size_t)e * 32768 + chunk * 16 * 64;
                        __syncthreads();
                        #pragma unroll
                        for (int j = 0; j < 2; j++) {
                            int idx = j * 512 + tid;
                            int r = idx >> 6, nq = idx & 63;
                            *(float4*)&cs[r][nq * 4] = s4[r * 64 + nq];
                        }
                        __syncthreads();
                        uint32_t v[4];
                        #pragma unroll
                        for (int q = 0; q < 4; q++) {
                            int W = tid * 4 + q;
                            int jg = W >> 6, li = (W & 63) >> 1, regi = W & 1;
                            int n = jg * 8 + (li >> 2);
                            int klo = 2 * ((li & 3) + 4 * regi);
                            v[q] = packh2(cs[klo][n], cs[klo + 1][n]);
                        }
                        ((uint4*)dst)[(size_t)e * 16384 + chunk * 512 + tid] =
                            make_uint4(v[0], v[1], v[2], v[3]);
                    }
                }
            } else {
                // 2 k16-chunks of w2
                for (int cc = 0; cc < 2; cc++) {
                    const int chunk = (s - 8) * 2 + cc;
                    const float4* s4 = (const float4*)w2 +
                                       (size_t)e * 32768 + chunk * 16 * 128;
                    __syncthreads();
                    #pragma unroll
                    for (int j = 0; j < 4; j++) {
                        int idx = j * 512 + tid;
                        int r = idx >> 7, nq = idx & 127;
                        *(float4*)&cs[r][nq * 4] = s4[r * 128 + nq];
                    }
                    __syncthreads();
                    #pragma unroll
                    for (int u = 0; u < 2; u++) {
                        uint32_t v[4];
                        #pragma unroll
                        for (int q = 0; q < 4; q++) {
                            int W = (tid * 2 + u) * 4 + q;
                            int jg = W >> 6, li = (W & 63) >> 1, regi = W & 1;
                            int n = jg * 8 + (li >> 2);
                            int klo = 2 * ((li & 3) + 4 * regi);
                            v[q] = packh2(cs[klo][n], cs[klo + 1][n]);
                        }
                        ((uint4*)g_w2h)[(size_t)e * 16384 + chunk * 1024 +
                                        tid * 2 + u] = make_uint4(v[0], v[1], v[2], v[3]);
                    }
                }
            }
            __syncthreads();
            if (tid == 0) { __threadfence(); atomicAdd(&g_ready[e], 1); }
            continue;
        }

        // ---------------- tile item: e = t>>4, slot = t&15 ------------------
        const int t   = item - 1024;
        const int e   = t >> 4;
        const int r0  = (t & 15) * 64;
        const int cnt = min(g_count[e], CAP);
        if (r0 >= cnt) continue;
        const int nr = min(ROWT, cnt - r0);

        if (tid == 0) {
            while (*(volatile int*)&g_ready[e] < 16) {}
            __threadfence();
        }
        __syncthreads();

        if (tid < ROWT) {
            rows_s[tid] = (tid < nr) ? g_rows[e][r0 + tid] : 0;
            wt_s[tid]   = (tid < nr) ? g_wt[e][r0 + tid]   : 0.0f;
        }
        __syncthreads();

        const uint32_t* xsrc = g_xh + (size_t)rows_s[xrow] * 256 + xkp;
        const uint32_t* w1p = g_w1h + (size_t)e * 65536;
        const uint32_t* w3p = g_w3h + (size_t)e * 65536;
        const uint32_t* w2p = g_w2h + (size_t)e * 65536;

        // =================== Phase A: 32 k16 chunks ===================
        float accA[2][4][2][4] = {};

        auto stageA = [&](int c, int b) {
            uint32_t base = smem_b + (128 + b * STA) * 4;
            CP16(base + tid * 16, w1p + c * 2048 + tid * 4);
            CP16(base + 8192 + tid * 16, w3p + c * 2048 + tid * 4);
            CP4(base + 16384 + xw, xsrc + c * 8);
        };

        #pragma unroll
        for (int p = 0; p < 7; p++) { stageA(p, p); CP_COMMIT(); }

        for (int c = 0; c < 32; c++) {
            const int b = c & 7;
            CP_WAIT6();
            __syncthreads();
            if (c + 7 < 32) stageA(c + 7, (c + 7) & 7);
            CP_COMMIT();

            const int sb0 = 128 + b * STA;
            uint4 a[2];
            #pragma unroll
            for (int m = 0; m < 2; m++)
                a[m] = *(const uint4*)&sm[sb0 + 4096 + (mg * 2 + m) * 128 + lane * 4];
            #pragma unroll
            for (int mat = 0; mat < 2; mat++) {
                #pragma unroll
                for (int j = 0; j < 4; j++) {
                    uint2 bv = *(const uint2*)&sm[sb0 + mat * 2048 +
                                                  (nw * 4 + j) * 64 + lane * 2];
                    mma16(accA[mat][j][0], a[0].x, a[0].y, a[0].z, a[0].w, bv.x, bv.y);
                    mma16(accA[mat][j][1], a[1].x, a[1].y, a[1].z, a[1].w, bv.x, bv.y);
                }
            }
        }
        CP_WAIT0();

        // ========== SwiGLU -> H planes ==========
        #pragma unroll
        for (int j = 0; j < 4; j++) {
            #pragma unroll
            for (int m = 0; m < 2; m++) {
                float h[4];
                #pragma unroll
                for (int r = 0; r < 4; r++) {
                    float v1 = accA[0][j][m][r];
                    float v3 = accA[1][j][m][r];
                    h[r] = v1 / (1.0f + __expf(-v1)) * v3;
                }
                const int base = HBW + ((nw * 2 + (j >> 1)) * 4 + mg * 2 + m) * 128 +
                                 lane * 4 + 2 * (j & 1);
                *(uint2*)&sm[base] = make_uint2(packh2(h[0], h[1]), packh2(h[2], h[3]));
            }
        }

        // =================== Phase B: 16 k16 chunks ===================
        float accB[8][2][4] = {};

        auto stageB = [&](int c, int b) {
            uint32_t base = smem_b + (128 + b * STB) * 4;
            CP16(base + tid * 16, w2p + c * 4096 + tid * 4);
            CP16(base + 8192 + tid * 16, w2p + c * 4096 + 2048 + tid * 4);
        };

        #pragma unroll
        for (int p = 0; p < 7; p++) { stageB(p, p); CP_COMMIT(); }

        for (int c = 0; c < 16; c++) {
            const int b = c & 7;
            CP_WAIT6();
            __syncthreads();
            if (c + 7 < 16) stageB(c + 7, (c + 7) & 7);
            CP_COMMIT();

            uint4 a[2];
            #pragma unroll
            for (int m = 0; m < 2; m++)
                a[m] = *(const uint4*)&sm[HBW + (c * 4 + mg * 2 + m) * 128 + lane * 4];
            const int sb0 = 128 + b * STB;
            #pragma unroll
            for (int j = 0; j < 8; j++) {
                uint2 bv = *(const uint2*)&sm[sb0 + (nw * 8 + j) * 64 + lane * 2];
                mma16(accB[j][0], a[0].x, a[0].y, a[0].z, a[0].w, bv.x, bv.y);
                mma16(accB[j][1], a[1].x, a[1].y, a[1].z, a[1].w, bv.x, bv.y);
            }
        }
        CP_WAIT0();

        // =================== Epilogue ===================
        #pragma unroll
        for (int m = 0; m < 2; m++) {
            #pragma unroll
            for (int rh = 0; rh < 2; rh++) {
                int row = mg * 32 + m * 16 + g + 8 * rh;
                if (row < nr) {
                    float wgt = wt_s[row];
                    float* op = out + (size_t)rows_s[row] * DIM;
                    #pragma unroll
                    for (int j = 0; j < 8; j++) {
                        int col = nw * 64 + j * 8 + tig * 2;
                        atomicAdd(op + col,     accB[j][m][rh * 2]     * wgt);
                        atomicAdd(op + col + 1, accB[j][m][rh * 2 + 1] * wgt);
                    }
                }
            }
        }
    }
}

// ---------------------------------------------------------------------------
extern "C" void kernel_launch(void* const* d_in, const int* in_sizes, int n_in,
                              void* d_out, int out_size) {
    const float* x      = (const float*)d_in[0];
    const float* gate_w = (const float*)d_in[1];
    const float* gate_b = (const float*)d_in[2];
    const float* w1     = (const float*)d_in[3];
    const float* w3     = (const float*)d_in[4];
    const float* w2     = (const float*)d_in[5];
    float* out = (float*)d_out;

    cudaFuncSetAttribute(moe_kernel, cudaFuncAttributeMaxDynamicSharedMemorySize, FFN_SMEM);

    zero_small<<<1, 128>>>();
    moe_kernel<<<NCTA, THREADS, FFN_SMEM>>>(x, gate_w, gate_b, w1, w3, w2, out);
}

// round 10
// speedup vs baseline: 1.1097x; 1.1097x over previous
#include <cuda_runtime.h>
#include <cuda_fp16.h>
#include <stdint.h>
#include <math.h>

#define T_TOK 2048
#define DIM   512
#define MOE   256
#define NE    64
#define NG    8
#define TOPKG 4
#define KSEL  8
#define RSCALE 2.5f
#define CAP   1024
#define ROWT  64
#define THREADS 512
#define NTILES 1024

__device__ int   g_count[NE];
__device__ int   g_rows[NE][CAP];
__device__ float g_wt[NE][CAP];
__device__ int   g_tile;

// fp16 panels (vector-fragment order), packed half2 words. 65536 words/expert.
__device__ uint32_t g_w1h[NE * 65536];
__device__ uint32_t g_w3h[NE * 65536];
__device__ uint32_t g_w2h[NE * 65536];
__device__ uint32_t g_xh[T_TOK * 256];

// ---------------------------------------------------------------------------
// ffn smem word map:
//  [0,64) rows_s  [64,128) wt_s
//  ring base 128: 4 slots, each slot = k32 stage
//   phase A slot stride 9216 (= 2 x (W1 2048 | W3 2048 | X 512))
//   phase B slot stride 8192 (= 2 x (W2 4096)) overlaid
//  HBW = 128 + 4*9216 = 36992 : H planes 16c x 4mf x 128 = 8192 words
// ---------------------------------------------------------------------------
#define SLOTA 9216
#define SLOTB 8192
#define SUBA  4608
#define SUBB  4096
#define HBW   36992
#define SMEM_W (36992 + 8192)
#define FFN_SMEM (SMEM_W * 4)

#define CP16(dst_b, src) \
    asm volatile("cp.async.cg.shared.global [%0], [%1], 16;" :: "r"(dst_b), "l"(src))
#define CP4(dst_b, src) \
    asm volatile("cp.async.ca.shared.global [%0], [%1], 4;" :: "r"(dst_b), "l"(src))
#define CP_COMMIT() asm volatile("cp.async.commit_group;" ::: "memory")
#define CP_WAIT2()  asm volatile("cp.async.wait_group 2;" ::: "memory")
#define CP_WAIT0()  asm volatile("cp.async.wait_group 0;" ::: "memory")

__device__ __forceinline__ uint32_t packh2(float lo, float hi) {
    __half2 h = __floats2half2_rn(lo, hi);
    return *(uint32_t*)&h;
}
__device__ __forceinline__ void mma16(float* d, uint32_t a0, uint32_t a1,
                                      uint32_t a2, uint32_t a3,
                                      uint32_t b0, uint32_t b1) {
    asm volatile(
        "mma.sync.aligned.m16n8k16.row.col.f32.f16.f16.f32 "
        "{%0,%1,%2,%3}, {%4,%5,%6,%7}, {%8,%9}, {%0,%1,%2,%3};"
        : "+f"(d[0]), "+f"(d[1]), "+f"(d[2]), "+f"(d[3])
        : "r"(a0), "r"(a1), "r"(a2), "r"(a3), "r"(b0), "r"(b1));
}

// ---------------------------------------------------------------------------
__global__ void zero_small() {
    if (threadIdx.x < NE) g_count[threadIdx.x] = 0;
    if (threadIdx.x == NE) g_tile = 0;
}

// ---------------------------------------------------------------------------
// prep+gate (R8 proven).  256 threads/block.  dyn smem 8256 floats.
// blocks: [0,2048) w1 | [2048,4096) w3 | [4096,5120) w2 |
//         [5120,7168) x | [7168,8192) zero out | [8192,8704) gate (4 tok/blk)
// ---------------------------------------------------------------------------
__global__ __launch_bounds__(256) void prep_gate_kernel(
    const float* __restrict__ w1,
    const float* __restrict__ w3,
    const float* __restrict__ w2,
    const float2* __restrict__ x2,
    const float* __restrict__ gate_w,
    const float* __restrict__ gate_b,
    float4* __restrict__ out)
{
    extern __shared__ float ps[];
    const int b = blockIdx.x;
    const int tid = threadIdx.x;

    if (b < 4096) {                       // ---- w1 / w3 ----
        float (*s)[516] = (float(*)[516])ps;
        const float* src = (b < 2048) ? w1 : w3;
        uint32_t*    dst = (b < 2048) ? g_w1h : g_w3h;
        const int id = b & 2047;
        const int e = id >> 5, chunk = id & 31;
        const float4* s4 = (const float4*)src + (size_t)e * 32768 + chunk * 16 * 64;
        #pragma unroll
        for (int j = 0; j < 4; j++) {
            int idx = j * 256 + tid;
            int r = idx >> 6, nq = idx & 63;
            *(float4*)&s[r][nq * 4] = s4[r * 64 + nq];
        }
        __syncthreads();
        uint4* d4 = (uint4*)dst + (size_t)e * 16384 + chunk * 512;
        #pragma unroll
        for (int u = 0; u < 2; u++) {
            uint32_t v[4];
            #pragma unroll
            for (int q = 0; q < 4; q++) {
                int W = (tid * 2 + u) * 4 + q;
                int jg = W >> 6, li = (W & 63) >> 1, regi = W & 1;
                int n = jg * 8 + (li >> 2);
                int klo = 2 * ((li & 3) + 4 * regi);
                v[q] = packh2(s[klo][n], s[klo + 1][n]);
            }
            d4[tid * 2 + u] = make_uint4(v[0], v[1], v[2], v[3]);
        }
    } else if (b < 5120) {                // ---- w2 ----
        float (*s)[516] = (float(*)[516])ps;
        const int id = b - 4096;
        const int e = id >> 4, chunk = id & 15;
        const float4* s4 = (const float4*)w2 + (size_t)e * 32768 + chunk * 16 * 128;
        #pragma unroll
        for (int j = 0; j < 8; j++) {
            int idx = j * 256 + tid;
            int r = idx >> 7, nq = idx & 127;
            *(float4*)&s[r][nq * 4] = s4[r * 128 + nq];
        }
        __syncthreads();
        uint4* d4 = (uint4*)g_w2h + (size_t)e * 16384 + chunk * 1024;
        #pragma unroll
        for (int u = 0; u < 4; u++) {
            uint32_t v[4];
            #pragma unroll
            for (int q = 0; q < 4; q++) {
                int W = (tid * 4 + u) * 4 + q;
                int jg = W >> 6, li = (W & 63) >> 1, regi = W & 1;
                int n = jg * 8 + (li >> 2);
                int klo = 2 * ((li & 3) + 4 * regi);
                v[q] = packh2(s[klo][n], s[klo + 1][n]);
            }
            d4[tid * 4 + u] = make_uint4(v[0], v[1], v[2], v[3]);
        }
    } else if (b < 7168) {                // ---- x ----
        int i = (b - 5120) * 256 + tid;
        float2 v = x2[i];
        g_xh[i] = packh2(v.x, v.y);
    } else if (b < 8192) {                // ---- zero out ----
        out[(b - 7168) * 256 + tid] = make_float4(0.f, 0.f, 0.f, 0.f);
    } else {                              // ---- gate: 4 tokens/block ----
        float* xs     = ps;               // [4][512]
        float (*gws)[68] = (float(*)[68])(ps + 2048);   // [64][68]
        float* scores = ps + 6400;        // [4][64]
        float* sb     = ps + 6656;        // [4][64]

        const int t0  = (b - 8192) * 4;
        const int tg  = tid >> 6, te = tid & 63;
        const float* x = (const float*)x2;

        const float4* xr = (const float4*)(x + (size_t)(t0 + tg) * DIM);
        ((float4*)(xs + tg * DIM))[te]      = xr[te];
        ((float4*)(xs + tg * DIM))[64 + te] = xr[64 + te];
        __syncthreads();

        float acc = 0.0f;
        const float4* gw4 = (const float4*)gate_w;
        for (int kc = 0; kc < DIM; kc += 64) {
            __syncthreads();
            #pragma unroll
            for (int j = 0; j < 4; j++) {
                int idx = j * 256 + tid;
                int e   = idx >> 4;
                int m4  = idx & 15;
                *(float4*)&gws[e][m4 * 4] = gw4[(size_t)e * (DIM/4) + (kc >> 2) + m4];
            }
            __syncthreads();
            #pragma unroll
            for (int kk = 0; kk < 64; kk += 4) {
                float4 wv = *(float4*)&gws[te][kk];
                float4 xv = *(float4*)&xs[tg * DIM + kc + kk];
                acc += xv.x * wv.x + xv.y * wv.y + xv.z * wv.z + xv.w * wv.w;
            }
        }
        float sc = 1.0f / (1.0f + expf(-acc));
        scores[tg * 64 + te] = sc;
        sb[tg * 64 + te]     = sc + gate_b[te];
        __syncthreads();

        if (te == 0) {
            float* sbT = sb + tg * 64;
            float* scT = scores + tg * 64;
            const int t = t0 + tg;
            const float NEG = -3.0e38f;
            float gsc[NG];
            #pragma unroll
            for (int g = 0; g < NG; g++) {
                float m1 = NEG, m2 = NEG;
                #pragma unroll
                for (int j = 0; j < 8; j++) {
                    float v = sbT[g * 8 + j];
                    if (v > m1) { m2 = m1; m1 = v; }
                    else if (v > m2) { m2 = v; }
                }
                gsc[g] = m1 + m2;
            }
            bool gsel[NG];
            #pragma unroll
            for (int g = 0; g < NG; g++) gsel[g] = false;
            for (int it = 0; it < TOPKG; it++) {
                int bg = -1; float bv = NEG;
                #pragma unroll
                for (int g = 0; g < NG; g++)
                    if (!gsel[g] && gsc[g] > bv) { bv = gsc[g]; bg = g; }
                gsel[bg] = true;
            }
            for (int e = 0; e < NE; e++)
                if (!gsel[e >> 3]) sbT[e] = NEG;
            int   idxs[KSEL];
            float wts[KSEL];
            float wsum = 0.0f;
            for (int k = 0; k < KSEL; k++) {
                int bi = 0; float bv = NEG;
                for (int e = 0; e < NE; e++)
                    if (sbT[e] > bv) { bv = sbT[e]; bi = e; }
                sbT[bi] = NEG;
                idxs[k] = bi;
                wts[k]  = scT[bi];
                wsum   += wts[k];
            }
            float inv = RSCALE / wsum;
            for (int k = 0; k < KSEL; k++) {
                int e = idxs[k];
                int pos = atomicAdd(&g_count[e], 1);
                if (pos < CAP) {
                    g_rows[e][pos] = t;
                    g_wt[e][pos]   = wts[k] * inv;
                }
            }
        }
    }
}

// ---------------------------------------------------------------------------
// FFN: persistent, mma.sync fp16 m16n8k16, k32 per pipeline stage (half the
// barriers of R8), 4-slot ring.
// ---------------------------------------------------------------------------
__global__ __launch_bounds__(THREADS, 1) void ffn_mma_kernel(
    float* __restrict__ out)
{
    extern __shared__ uint32_t sm[];
    __shared__ int cur_t;

    const int tid  = threadIdx.x;
    const int lane = tid & 31, wid = tid >> 5;
    const int g    = lane >> 2, tig = lane & 3;
    const int mg   = wid >> 3, nw = wid & 7;

    uint32_t smem_b;
    asm("{ .reg .u64 t; cvta.to.shared.u64 t, %1; cvt.u32.u64 %0, t; }"
        : "=r"(smem_b) : "l"(sm));

    const int xrow = tid >> 3, xkp = tid & 7;
    const uint32_t xw = ((xrow >> 4) * 128 + ((xrow & 7) * 4 + (xkp & 3)) * 4 +
                        ((xrow >> 3) & 1) + 2 * (xkp >> 2)) * 4;

    int*   rows_s = (int*)sm;
    float* wt_s   = (float*)(sm + 64);

    for (;;) {
        __syncthreads();
        if (tid == 0) cur_t = atomicAdd(&g_tile, 1);
        __syncthreads();
        const int t = cur_t;
        if (t >= NTILES) break;

        const int e   = t & 63;
        const int r0  = (t >> 6) * 64;
        const int cnt = min(g_count[e], CAP);
        if (r0 >= cnt) continue;
        const int nr = min(ROWT, cnt - r0);

        if (tid < ROWT) {
            rows_s[tid] = (tid < nr) ? g_rows[e][r0 + tid] : 0;
            wt_s[tid]   = (tid < nr) ? g_wt[e][r0 + tid]   : 0.0f;
        }
        __syncthreads();

        const uint32_t* xsrc = g_xh + (size_t)rows_s[xrow] * 256 + xkp;
        const uint32_t* w1p = g_w1h + (size_t)e * 65536;
        const uint32_t* w3p = g_w3h + (size_t)e * 65536;
        const uint32_t* w2p = g_w2h + (size_t)e * 65536;

        // =================== Phase A: 16 stages of k32 ===================
        float accA[2][4][2][4] = {};

        auto stageA = [&](int s, int b) {
            uint32_t base = smem_b + (128 + b * SLOTA) * 4;
            #pragma unroll
            for (int cc = 0; cc < 2; cc++) {
                const int c = s * 2 + cc;
                uint32_t off = base + cc * SUBA * 4;
                CP16(off + tid * 16, w1p + c * 2048 + tid * 4);
                CP16(off + 8192 + tid * 16, w3p + c * 2048 + tid * 4);
                CP4(off + 16384 + xw, xsrc + c * 8);
            }
        };

        #pragma unroll
        for (int p = 0; p < 3; p++) { stageA(p, p); CP_COMMIT(); }

        for (int s = 0; s < 16; s++) {
            const int b = s & 3;
            CP_WAIT2();
            __syncthreads();
            if (s + 3 < 16) stageA(s + 3, (s + 3) & 3);
            CP_COMMIT();

            #pragma unroll
            for (int cc = 0; cc < 2; cc++) {
                const int sb0 = 128 + b * SLOTA + cc * SUBA;
                uint4 a[2];
                #pragma unroll
                for (int m = 0; m < 2; m++)
                    a[m] = *(const uint4*)&sm[sb0 + 4096 + (mg * 2 + m) * 128 + lane * 4];
                #pragma unroll
                for (int mat = 0; mat < 2; mat++) {
                    #pragma unroll
                    for (int j = 0; j < 4; j++) {
                        uint2 bv = *(const uint2*)&sm[sb0 + mat * 2048 +
                                                      (nw * 4 + j) * 64 + lane * 2];
                        mma16(accA[mat][j][0], a[0].x, a[0].y, a[0].z, a[0].w, bv.x, bv.y);
                        mma16(accA[mat][j][1], a[1].x, a[1].y, a[1].z, a[1].w, bv.x, bv.y);
                    }
                }
            }
        }
        CP_WAIT0();

        // ========== SwiGLU -> H planes (STS.64 each) ==========
        #pragma unroll
        for (int j = 0; j < 4; j++) {
            #pragma unroll
            for (int m = 0; m < 2; m++) {
                float h[4];
                #pragma unroll
                for (int r = 0; r < 4; r++) {
                    float v1 = accA[0][j][m][r];
                    float v3 = accA[1][j][m][r];
                    h[r] = v1 / (1.0f + __expf(-v1)) * v3;
                }
                const int base = HBW + ((nw * 2 + (j >> 1)) * 4 + mg * 2 + m) * 128 +
                                 lane * 4 + 2 * (j & 1);
                *(uint2*)&sm[base] = make_uint2(packh2(h[0], h[1]), packh2(h[2], h[3]));
            }
        }

        // =================== Phase B: 8 stages of k32 ===================
        float accB[8][2][4] = {};

        auto stageB = [&](int s, int b) {
            uint32_t base = smem_b + (128 + b * SLOTB) * 4;
            #pragma unroll
            for (int cc = 0; cc < 2; cc++) {
                const int c = s * 2 + cc;
                uint32_t off = base + cc * SUBB * 4;
                CP16(off + tid * 16, w2p + c * 4096 + tid * 4);
                CP16(off + 8192 + tid * 16, w2p + c * 4096 + 2048 + tid * 4);
            }
        };

        #pragma unroll
        for (int p = 0; p < 3; p++) { stageB(p, p); CP_COMMIT(); }

        for (int s = 0; s < 8; s++) {
            const int b = s & 3;
            CP_WAIT2();
            __syncthreads();
            if (s + 3 < 8) stageB(s + 3, (s + 3) & 3);
            CP_COMMIT();

            #pragma unroll
            for (int cc = 0; cc < 2; cc++) {
                const int c = s * 2 + cc;
                uint4 a[2];
                #pragma unroll
                for (int m = 0; m < 2; m++)
                    a[m] = *(const uint4*)&sm[HBW + (c * 4 + mg * 2 + m) * 128 + lane * 4];
                const int sb0 = 128 + b * SLOTB + cc * SUBB;
                #pragma unroll
                for (int j = 0; j < 8; j++) {
                    uint2 bv = *(const uint2*)&sm[sb0 + (nw * 8 + j) * 64 + lane * 2];
                    mma16(accB[j][0], a[0].x, a[0].y, a[0].z, a[0].w, bv.x, bv.y);
                    mma16(accB[j][1], a[1].x, a[1].y, a[1].z, a[1].w, bv.x, bv.y);
                }
            }
        }
        CP_WAIT0();

        // =================== Epilogue ===================
        #pragma unroll
        for (int m = 0; m < 2; m++) {
            #pragma unroll
            for (int rh = 0; rh < 2; rh++) {
                int row = mg * 32 + m * 16 + g + 8 * rh;
                if (row < nr) {
                    float wgt = wt_s[row];
                    float* op = out + (size_t)rows_s[row] * DIM;
                    #pragma unroll
                    for (int j = 0; j < 8; j++) {
                        int col = nw * 64 + j * 8 + tig * 2;
                        atomicAdd(op + col,     accB[j][m][rh * 2]     * wgt);
                        atomicAdd(op + col + 1, accB[j][m][rh * 2 + 1] * wgt);
                    }
                }
            }
        }
    }
}

// ---------------------------------------------------------------------------
extern "C" void kernel_launch(void* const* d_in, const int* in_sizes, int n_in,
                              void* d_out, int out_size) {
    const float* x      = (const float*)d_in[0];
    const float* gate_w = (const float*)d_in[1];
    const float* gate_b = (const float*)d_in[2];
    const float* w1     = (const float*)d_in[3];
    const float* w3     = (const float*)d_in[4];
    const float* w2     = (const float*)d_in[5];
    float* out = (float*)d_out;

    cudaFuncSetAttribute(ffn_mma_kernel, cudaFuncAttributeMaxDynamicSharedMemorySize, FFN_SMEM);

    zero_small<<<1, 128>>>();
    prep_gate_kernel<<<8704, 256, 8256 * 4>>>(
        w1, w3, w2, (const float2*)x, gate_w, gate_b, (float4*)out);
    ffn_mma_kernel<<<152, THREADS, FFN_SMEM>>>(out);
}